// round 14
// baseline (speedup 1.0000x reference)
#include <cuda_runtime.h>
#include <cuda_fp16.h>

// AbstractConv3D: 16 levels, dense R^3 grids, 3x3x3 conv, Cin=Cout=16, B=2.
// R14: fp16 m16n8k16 with transposed roles (R13 + staging-address fix):
// A = weights (16co x 16ci): one LDS.128/tap = native 4-reg A-frag.
// B = voxels (16ci x 8w):    one LDS.64/h-row = native (b0,b1) B-frag.
// Zero register marshaling. BUGFIX vs R13: input staging now stores granules
// at the PADDED index dz*110 + hy*11 + wx (was v=dz*100+hy*10+wx, which the
// main loop never read).

#define NLEV 16
#define TPB 256
#define TOTAL_N 1844282

__constant__ int c_res[NLEV]  = {16,18,20,22,24,27,30,34,38,42,47,52,58,64,72,80};
__constant__ int c_off[NLEV]  = {0,4096,9928,17928,28576,42400,62083,89083,128387,
                                 183259,257347,361170,501778,696890,959034,1332282};
__constant__ int c_nt[NLEV]   = {2,3,3,3,3,4,4,5,5,6,6,7,8,8,9,10};   // ceil(R/8)
__constant__ int c_tblk[NLEV+1] = {0,8,35,62,89,116,180,244,369,494,710,926,
                                   1269,1781,2293,3022,4022};

// smem (bytes):
// [0,13824)      weights A-frag native: [tap][lane][a0..a3] = 27*512
// [13824,13888)  bias f32
// [13888,49088)  input tile fp16: 1100 granules x 32B (padded rows of 11)
//   granule g = dz*110 + hy*11 + wx ; byte c*8: (ci 2c,2c+1),(ci 2c+8,2c+9)
#define SM_W    0
#define SM_BIAS 13824
#define SM_A    13888
#define SM_TOTAL 49088

__device__ __forceinline__ unsigned smem_u32(const void* p) {
    unsigned a;
    asm("{ .reg .u64 t; cvta.to.shared.u64 t, %1; cvt.u32.u64 %0, t; }"
        : "=r"(a) : "l"(p));
    return a;
}
__device__ __forceinline__ unsigned packh2(float lo, float hi) {
    __half2 h = __floats2half2_rn(lo, hi);
    return *(unsigned*)&h;
}
__device__ __forceinline__ uint2 lds64(unsigned a) {
    uint2 v;
    asm volatile("ld.shared.v2.b32 {%0,%1}, [%2];" : "=r"(v.x), "=r"(v.y) : "r"(a));
    return v;
}
__device__ __forceinline__ uint4 lds128(unsigned a) {
    uint4 v;
    asm volatile("ld.shared.v4.b32 {%0,%1,%2,%3}, [%4];"
                 : "=r"(v.x), "=r"(v.y), "=r"(v.z), "=r"(v.w) : "r"(a));
    return v;
}
__device__ __forceinline__ void mma_f16(float* c, const uint4& a, const uint2& b) {
    asm volatile(
        "mma.sync.aligned.m16n8k16.row.col.f32.f16.f16.f32 "
        "{%0,%1,%2,%3}, {%4,%5,%6,%7}, {%8,%9}, {%0,%1,%2,%3};"
        : "+f"(c[0]), "+f"(c[1]), "+f"(c[2]), "+f"(c[3])
        : "r"(a.x), "r"(a.y), "r"(a.z), "r"(a.w), "r"(b.x), "r"(b.y));
}

__global__ __launch_bounds__(TPB, 3)
void conv3d_f16t2_kernel(const float* __restrict__ in,
                         const float* __restrict__ wgt,
                         const float* __restrict__ bias,
                         float* __restrict__ out) {
    extern __shared__ char smem[];
    const unsigned sbase = smem_u32(smem);
    const int tid = threadIdx.x;
    const int wid = tid >> 5;      // warp = d-plane (0..7)
    const int lane = tid & 31;
    const int r4 = lane >> 2;      // co row (A/C) ; voxel col n (B) (0..7)
    const int c4 = lane & 3;       // k-group (0..3)
    const int b = blockIdx.y;
    const int blk = blockIdx.x;

    // level + tile decode
    int l = 0;
#pragma unroll
    for (int i = 1; i < NLEV; i++)
        if (blk >= c_tblk[i]) l = i;
    const int lblk = blk - c_tblk[l];
    const int R = c_res[l];
    const int off = c_off[l];
    const int nt = c_nt[l];
    const int tz = lblk / (nt * nt);
    const int trem = lblk - tz * nt * nt;
    const int ty = trem / nt;
    const int tx = trem - ty * nt;

    // ---- stage weights as native A-fragments (A[m=co][k=ci] = W[ci][co]) ----
    // a0 = A[r4][2c4,2c4+1]  a1 = A[r4+8][2c4,2c4+1]
    // a2 = A[r4][2c4+8,+9]   a3 = A[r4+8][2c4+8,+9]
    {
        const float* wl = wgt + l * 6912;
        for (int tap = wid; tap < 27; tap += 8) {
            const float* wp = wl + tap * 256;
            const int ci0 = 2 * c4;
            const unsigned a0 = packh2(wp[ci0 * 16 + r4],     wp[(ci0 + 1) * 16 + r4]);
            const unsigned a1 = packh2(wp[ci0 * 16 + r4 + 8], wp[(ci0 + 1) * 16 + r4 + 8]);
            const unsigned a2 = packh2(wp[(ci0 + 8) * 16 + r4],     wp[(ci0 + 9) * 16 + r4]);
            const unsigned a3 = packh2(wp[(ci0 + 8) * 16 + r4 + 8], wp[(ci0 + 9) * 16 + r4 + 8]);
            asm volatile("st.shared.v4.b32 [%0], {%1,%2,%3,%4};"
                         :: "r"(sbase + SM_W + (unsigned)(tap * 512 + lane * 16)),
                            "r"(a0), "r"(a1), "r"(a2), "r"(a3) : "memory");
        }
        if (tid < 16)
            *(float*)(smem + SM_BIAS + tid * 4) = bias[l * 16 + tid];
    }

    // ---- stage input tile 10x10x10 (fp16, halo zero, coalesced lanes) ----
    // lane -> (voxel v = g0 + r4, chunk q = c4); 16B LDG per lane, two 4B STS
    // into the PADDED granule dz*110 + hy*11 + wx.
    {
        const int d0 = tz * 8 - 1, h0 = ty * 8 - 1, w0 = tx * 8 - 1;
        const float* inB = in + ((size_t)b * TOTAL_N + off) * 16;
        const int q = c4;
        const unsigned off1 = (q < 2) ? (unsigned)(q * 16) : (unsigned)((q - 2) * 16 + 4);
        for (int g0 = wid * 8; g0 < 1000; g0 += 64) {
            const int v = g0 + r4;
            const int dz = v / 100;
            const int rr = v - dz * 100;
            const int hy = rr / 10;
            const int wx = rr - hy * 10;
            const int dd = d0 + dz, hh = h0 + hy, ww = w0 + wx;
            unsigned p0 = 0u, p1 = 0u;
            if (((unsigned)dd < (unsigned)R) & ((unsigned)hh < (unsigned)R) &
                ((unsigned)ww < (unsigned)R)) {
                const float4 f = __ldg((const float4*)(inB +
                                 (size_t)((dd * R + hh) * R + ww) * 16) + q);
                p0 = packh2(f.x, f.y);
                p1 = packh2(f.z, f.w);
            }
            // BUGFIX: padded granule index (was v*32)
            const unsigned g32 = sbase + SM_A +
                (unsigned)(dz * 110 + hy * 11 + wx) * 32 + off1;
            asm volatile("st.shared.b32 [%0], %1;" :: "r"(g32), "r"(p0) : "memory");
            asm volatile("st.shared.b32 [%0], %1;" :: "r"(g32 + 8), "r"(p1) : "memory");
        }
    }
    __syncthreads();

    // ---- accumulators [h-row o][4]: c0/c1 = co r4 @ voxels 2c4,2c4+1 ;
    //                                 c2/c3 = co r4+8 ----
    float acc[8][4];
    {
        const float* bs = (const float*)(smem + SM_BIAS);
        const float bl = bs[r4], bh = bs[r4 + 8];
#pragma unroll
        for (int o = 0; o < 8; o++) {
            acc[o][0] = bl; acc[o][1] = bl;
            acc[o][2] = bh; acc[o][3] = bh;
        }
    }

    const unsigned wBase = sbase + SM_W + (unsigned)(lane * 16);
    const unsigned aBase = sbase + SM_A + (unsigned)(r4 * 32 + c4 * 8);

#pragma unroll
    for (int kd = 0; kd < 3; kd++) {
#pragma unroll
        for (int kw = 0; kw < 3; kw++) {
            const unsigned rb = aBase + (unsigned)(((wid + kd) * 110 + kw) * 32);
            uint2 rw[10];
#pragma unroll
            for (int r = 0; r < 10; r++)
                rw[r] = lds64(rb + (unsigned)(r * 352));
#pragma unroll
            for (int kh = 0; kh < 3; kh++) {
                const uint4 af = lds128(wBase + (unsigned)((kd * 9 + kh * 3 + kw) * 512));
#pragma unroll
                for (int o = 0; o < 8; o++)
                    mma_f16(acc[o], af, rw[o + kh]);
            }
        }
    }

    // ---- epilogue: thread writes co (r4, r4+8) at voxels (o, 2c4 / 2c4+1) ----
    const int od = tz * 8 + wid;
    const int ow0 = tx * 8 + 2 * c4;
    float* outB = out + ((size_t)b * TOTAL_N + off) * 16;
    if (od < R) {
        const bool k0 = ow0 < R;
        const bool k1 = ow0 + 1 < R;
#pragma unroll
        for (int o = 0; o < 8; o++) {
            const int oh = ty * 8 + o;
            if (oh >= R) continue;
            float* pb = outB + (size_t)((od * R + oh) * R) * 16;
            if (k0) {
                pb[(size_t)ow0 * 16 + r4]     = acc[o][0];
                pb[(size_t)ow0 * 16 + r4 + 8] = acc[o][2];
            }
            if (k1) {
                pb[(size_t)(ow0 + 1) * 16 + r4]     = acc[o][1];
                pb[(size_t)(ow0 + 1) * 16 + r4 + 8] = acc[o][3];
            }
        }
    }
}

extern "C" void kernel_launch(void* const* d_in, const int* in_sizes, int n_in,
                              void* d_out, int out_size) {
    const float* in   = (const float*)d_in[0];
    const float* wgt  = (const float*)d_in[1];
    const float* bias = (const float*)d_in[2];
    float* out = (float*)d_out;

    static int configured = 0;
    if (!configured) {
        cudaFuncSetAttribute(conv3d_f16t2_kernel,
                             cudaFuncAttributeMaxDynamicSharedMemorySize,
                             SM_TOTAL);
        configured = 1;
    }

    dim3 grid(4022, 2);
    conv3d_f16t2_kernel<<<grid, TPB, SM_TOTAL>>>(in, wgt, bias, out);
}

// round 15
// speedup vs baseline: 1.2042x; 1.2042x over previous
#include <cuda_runtime.h>
#include <cuda_fp16.h>

// AbstractConv3D: 16 levels, dense R^3 grids, 3x3x3 conv, Cin=Cout=16, B=2.
// R15: R12's validated fp16 m16n8k16 core (voxels=A, weights=B), restructured
// for 4 CTAs/SM: h-row streaming (2-row register window instead of rowF[10]),
// weights prefetched as 3x LDS.128 per (kd,kw) (nh0|nh1 packed per tap),
// coalesced input staging. Target <=64 regs -> 32 warps/SM.

#define NLEV 16
#define TPB 256
#define TOTAL_N 1844282

__constant__ int c_res[NLEV]  = {16,18,20,22,24,27,30,34,38,42,47,52,58,64,72,80};
__constant__ int c_off[NLEV]  = {0,4096,9928,17928,28576,42400,62083,89083,128387,
                                 183259,257347,361170,501778,696890,959034,1332282};
__constant__ int c_nt[NLEV]   = {2,3,3,3,3,4,4,5,5,6,6,7,8,8,9,10};   // ceil(R/8)
__constant__ int c_tblk[NLEV+1] = {0,8,35,62,89,116,180,244,369,494,710,926,
                                   1269,1781,2293,3022,4022};

// smem (bytes):
// [0,13824)     weights: [tap][lane][16B = b0nh0,b1nh0,b0nh1,b1nh1] = 27*512
// [13824,13888) bias f32
// [13888,49088) input tile fp16: 1100 granules x 32B (padded rows of 11)
//   granule g = dz*110 + hy*11 + wx
//   granule bytes: p[2c]=(f[2c],f[2c+1]) @8c ; p[2c+1]=(f[2c+8],f[2c+9]) @8c+4
#define SM_W    0
#define SM_BIAS 13824
#define SM_A    13888
#define SM_TOTAL 49088

__device__ __forceinline__ unsigned smem_u32(const void* p) {
    unsigned a;
    asm("{ .reg .u64 t; cvta.to.shared.u64 t, %1; cvt.u32.u64 %0, t; }"
        : "=r"(a) : "l"(p));
    return a;
}
__device__ __forceinline__ unsigned packh2(float lo, float hi) {
    __half2 h = __floats2half2_rn(lo, hi);
    return *(unsigned*)&h;
}
__device__ __forceinline__ uint2 lds64(unsigned a) {
    uint2 v;
    asm volatile("ld.shared.v2.b32 {%0,%1}, [%2];" : "=r"(v.x), "=r"(v.y) : "r"(a));
    return v;
}
__device__ __forceinline__ uint4 lds128(unsigned a) {
    uint4 v;
    asm volatile("ld.shared.v4.b32 {%0,%1,%2,%3}, [%4];"
                 : "=r"(v.x), "=r"(v.y), "=r"(v.z), "=r"(v.w) : "r"(a));
    return v;
}
__device__ __forceinline__ void mma_f16(float* c,
                                        unsigned a0, unsigned a1, unsigned a2, unsigned a3,
                                        unsigned b0, unsigned b1) {
    asm volatile(
        "mma.sync.aligned.m16n8k16.row.col.f32.f16.f16.f32 "
        "{%0,%1,%2,%3}, {%4,%5,%6,%7}, {%8,%9}, {%0,%1,%2,%3};"
        : "+f"(c[0]), "+f"(c[1]), "+f"(c[2]), "+f"(c[3])
        : "r"(a0), "r"(a1), "r"(a2), "r"(a3), "r"(b0), "r"(b1));
}

__global__ __launch_bounds__(TPB, 4)
void conv3d_f16s_kernel(const float* __restrict__ in,
                        const float* __restrict__ wgt,
                        const float* __restrict__ bias,
                        float* __restrict__ out) {
    extern __shared__ char smem[];
    const unsigned sbase = smem_u32(smem);
    const int tid = threadIdx.x;
    const int wid = tid >> 5;      // warp = d-plane (0..7)
    const int lane = tid & 31;
    const int r4 = lane >> 2;      // w voxel (A row) / co (B col)
    const int c4 = lane & 3;       // k-group (0..3)
    const int b = blockIdx.y;
    const int blk = blockIdx.x;

    // level + tile decode
    int l = 0;
#pragma unroll
    for (int i = 1; i < NLEV; i++)
        if (blk >= c_tblk[i]) l = i;
    const int lblk = blk - c_tblk[l];
    const int R = c_res[l];
    const int off = c_off[l];
    const int nt = c_nt[l];
    const int tz = lblk / (nt * nt);
    const int trem = lblk - tz * nt * nt;
    const int ty = trem / nt;
    const int tx = trem - ty * nt;

    // ---- stage weights: per (tap, lane) one 16B = both nh B-frags ----
    // b0nh = (W[2c4][8nh+r4], W[2c4+1][8nh+r4]), b1nh = (W[2c4+8][..], W[2c4+9][..])
    {
        const float* wl = wgt + l * 6912;
        const int ci0 = 2 * c4;
        for (int tap = wid; tap < 27; tap += 8) {
            const float* wp = wl + tap * 256;
            const unsigned b00 = packh2(wp[ci0 * 16 + r4],       wp[(ci0 + 1) * 16 + r4]);
            const unsigned b10 = packh2(wp[(ci0 + 8) * 16 + r4], wp[(ci0 + 9) * 16 + r4]);
            const unsigned b01 = packh2(wp[ci0 * 16 + r4 + 8],       wp[(ci0 + 1) * 16 + r4 + 8]);
            const unsigned b11 = packh2(wp[(ci0 + 8) * 16 + r4 + 8], wp[(ci0 + 9) * 16 + r4 + 8]);
            asm volatile("st.shared.v4.b32 [%0], {%1,%2,%3,%4};"
                         :: "r"(sbase + SM_W + (unsigned)(tap * 512 + lane * 16)),
                            "r"(b00), "r"(b10), "r"(b01), "r"(b11) : "memory");
        }
        if (tid < 16)
            *(float*)(smem + SM_BIAS + tid * 4) = bias[l * 16 + tid];
    }

    // ---- stage input tile 10x10x10 (fp16, halo zero, coalesced lanes) ----
    // lane -> (voxel v = g0 + r4, chunk q = c4): one 16B LDG, two 4B STS into
    // the padded granule (dz*110 + hy*11 + wx)*32.
    {
        const int d0 = tz * 8 - 1, h0 = ty * 8 - 1, w0 = tx * 8 - 1;
        const float* inB = in + ((size_t)b * TOTAL_N + off) * 16;
        const int q = c4;
        const unsigned off1 = (q < 2) ? (unsigned)(q * 16) : (unsigned)((q - 2) * 16 + 4);
        for (int g0 = wid * 8; g0 < 1000; g0 += 64) {
            const int v = g0 + r4;
            const int dz = v / 100;
            const int rr = v - dz * 100;
            const int hy = rr / 10;
            const int wx = rr - hy * 10;
            const int dd = d0 + dz, hh = h0 + hy, ww = w0 + wx;
            unsigned p0 = 0u, p1 = 0u;
            if (((unsigned)dd < (unsigned)R) & ((unsigned)hh < (unsigned)R) &
                ((unsigned)ww < (unsigned)R)) {
                const float4 f = __ldg((const float4*)(inB +
                                 (size_t)((dd * R + hh) * R + ww) * 16) + q);
                p0 = packh2(f.x, f.y);
                p1 = packh2(f.z, f.w);
            }
            const unsigned g32 = sbase + SM_A +
                (unsigned)(dz * 110 + hy * 11 + wx) * 32 + off1;
            asm volatile("st.shared.b32 [%0], %1;" :: "r"(g32), "r"(p0) : "memory");
            asm volatile("st.shared.b32 [%0], %1;" :: "r"(g32 + 8), "r"(p1) : "memory");
        }
    }
    __syncthreads();

    // ---- accumulators [h-pair j][nh][4] (R12 layout), bias-initialized ----
    float acc[4][2][4];
    {
        const float* bs = (const float*)(smem + SM_BIAS);
        float b00 = bs[2 * c4], b01 = bs[2 * c4 + 1];
        float b10 = bs[2 * c4 + 8], b11 = bs[2 * c4 + 9];
#pragma unroll
        for (int j = 0; j < 4; j++) {
            acc[j][0][0] = b00; acc[j][0][1] = b01; acc[j][0][2] = b00; acc[j][0][3] = b01;
            acc[j][1][0] = b10; acc[j][1][1] = b11; acc[j][1][2] = b10; acc[j][1][3] = b11;
        }
    }

    const unsigned aBase = sbase + SM_A + (unsigned)(r4 * 32 + c4 * 8);
    const unsigned wBase = sbase + SM_W + (unsigned)(lane * 16);

#define STEP(j, W)                                                              \
    mma_f16(acc[j][0], rA.x, rB.x, rA.y, rB.y, (W).x, (W).y);                   \
    mma_f16(acc[j][1], rA.x, rB.x, rA.y, rB.y, (W).z, (W).w);

    for (int kd = 0; kd < 3; kd++) {
        const unsigned pb = aBase + (unsigned)((wid + kd) * 110) * 32;
        const unsigned wkd = wBase + (unsigned)(kd * 9) * 512;
#pragma unroll
        for (int kw = 0; kw < 3; kw++) {
            const unsigned rb = pb + (unsigned)(kw * 32);
            // weights for the 3 kh taps of this (kd,kw): 3 LDS.128
            const uint4 w0 = lds128(wkd + (unsigned)(kw * 512));          // kh=0
            const uint4 w1 = lds128(wkd + (unsigned)((3 + kw) * 512));    // kh=1
            const uint4 w2 = lds128(wkd + (unsigned)((6 + kw) * 512));    // kh=2
            // stream h-rows 0..9 with a 2-row window
            uint2 rA = lds64(rb);
            uint2 rB;
            rB = lds64(rb + 352);  STEP(0, w0);                 rA = rB;  // h=0
            rB = lds64(rb + 704);  STEP(0, w1);                 rA = rB;  // h=1
            rB = lds64(rb + 1056); STEP(0, w2); STEP(1, w0);    rA = rB;  // h=2
            rB = lds64(rb + 1408); STEP(1, w1);                 rA = rB;  // h=3
            rB = lds64(rb + 1760); STEP(1, w2); STEP(2, w0);    rA = rB;  // h=4
            rB = lds64(rb + 2112); STEP(2, w1);                 rA = rB;  // h=5
            rB = lds64(rb + 2464); STEP(2, w2); STEP(3, w0);    rA = rB;  // h=6
            rB = lds64(rb + 2816); STEP(3, w1);                 rA = rB;  // h=7
            rB = lds64(rb + 3168); STEP(3, w2);                           // h=8
        }
    }
#undef STEP

    // ---- epilogue (R12 exact) ----
    const int ow = tx * 8 + r4;
    const int od = tz * 8 + wid;
    float* outB = out + ((size_t)b * TOTAL_N + off) * 16;
    if (ow < R && od < R) {
#pragma unroll
        for (int j = 0; j < 4; j++) {
#pragma unroll
            for (int hl = 0; hl < 2; hl++) {
                const int oh = ty * 8 + j * 2 + hl;
                if (oh >= R) continue;
                float* po = outB + (size_t)((od * R + oh) * R + ow) * 16;
                *(float2*)(po + 2 * c4)     = make_float2(acc[j][0][hl * 2], acc[j][0][hl * 2 + 1]);
                *(float2*)(po + 2 * c4 + 8) = make_float2(acc[j][1][hl * 2], acc[j][1][hl * 2 + 1]);
            }
        }
    }
}

extern "C" void kernel_launch(void* const* d_in, const int* in_sizes, int n_in,
                              void* d_out, int out_size) {
    const float* in   = (const float*)d_in[0];
    const float* wgt  = (const float*)d_in[1];
    const float* bias = (const float*)d_in[2];
    float* out = (float*)d_out;

    static int configured = 0;
    if (!configured) {
        cudaFuncSetAttribute(conv3d_f16s_kernel,
                             cudaFuncAttributeMaxDynamicSharedMemorySize,
                             SM_TOTAL);
        configured = 1;
    }

    dim3 grid(4022, 2);
    conv3d_f16s_kernel<<<grid, TPB, SM_TOTAL>>>(in, wgt, bias, out);
}

// round 16
// speedup vs baseline: 1.3447x; 1.1167x over previous
#include <cuda_runtime.h>
#include <cuda_fp16.h>

// AbstractConv3D: 16 levels, dense R^3 grids, 3x3x3 conv, Cin=Cout=16, B=2.
// R16: R15 base (fp16 m16n8k16, voxels=A/weights=B, 8^3 tile, 4 CTAs/SM) +
//  - depth-4 register rotation with 2-row LDS lookahead (no MOVs, latency hidden)
//  - pi-permuted k-mapping (ci{4q..4q+3} -> k{2q,2q+1,2q+8,2q+9}): staging is
//    one STS.64 per lane; weights re-indexed to match
//  - unpadded granule layout (g == linear v), incremental staging coords

#define NLEV 16
#define TPB 256
#define TOTAL_N 1844282

__constant__ int c_res[NLEV]  = {16,18,20,22,24,27,30,34,38,42,47,52,58,64,72,80};
__constant__ int c_off[NLEV]  = {0,4096,9928,17928,28576,42400,62083,89083,128387,
                                 183259,257347,361170,501778,696890,959034,1332282};
__constant__ int c_nt[NLEV]   = {2,3,3,3,3,4,4,5,5,6,6,7,8,8,9,10};   // ceil(R/8)
__constant__ int c_tblk[NLEV+1] = {0,8,35,62,89,116,180,244,369,494,710,926,
                                   1269,1781,2293,3022,4022};

// smem (bytes):
// [0,13824)     weights: [tap][lane][16B = b0nh0,b1nh0,b0nh1,b1nh1]
// [13824,13888) bias f32
// [13888,45888) input tile fp16: 1000 granules x 32B, granule g = dz*100+hy*10+wx
//   granule byte [8q..8q+8) = ci(4q,4q+1 | 4q+2,4q+3)  (pi k-mapping)
#define SM_W    0
#define SM_BIAS 13824
#define SM_A    13888
#define SM_TOTAL 45888

__device__ __forceinline__ unsigned smem_u32(const void* p) {
    unsigned a;
    asm("{ .reg .u64 t; cvta.to.shared.u64 t, %1; cvt.u32.u64 %0, t; }"
        : "=r"(a) : "l"(p));
    return a;
}
__device__ __forceinline__ unsigned packh2(float lo, float hi) {
    __half2 h = __floats2half2_rn(lo, hi);
    return *(unsigned*)&h;
}
__device__ __forceinline__ uint2 lds64(unsigned a) {
    uint2 v;
    asm volatile("ld.shared.v2.b32 {%0,%1}, [%2];" : "=r"(v.x), "=r"(v.y) : "r"(a));
    return v;
}
__device__ __forceinline__ uint4 lds128(unsigned a) {
    uint4 v;
    asm volatile("ld.shared.v4.b32 {%0,%1,%2,%3}, [%4];"
                 : "=r"(v.x), "=r"(v.y), "=r"(v.z), "=r"(v.w) : "r"(a));
    return v;
}
__device__ __forceinline__ void mma_f16(float* c,
                                        unsigned a0, unsigned a1, unsigned a2, unsigned a3,
                                        unsigned b0, unsigned b1) {
    asm volatile(
        "mma.sync.aligned.m16n8k16.row.col.f32.f16.f16.f32 "
        "{%0,%1,%2,%3}, {%4,%5,%6,%7}, {%8,%9}, {%0,%1,%2,%3};"
        : "+f"(c[0]), "+f"(c[1]), "+f"(c[2]), "+f"(c[3])
        : "r"(a0), "r"(a1), "r"(a2), "r"(a3), "r"(b0), "r"(b1));
}

__global__ __launch_bounds__(TPB, 4)
void conv3d_f16r_kernel(const float* __restrict__ in,
                        const float* __restrict__ wgt,
                        const float* __restrict__ bias,
                        float* __restrict__ out) {
    extern __shared__ char smem[];
    const unsigned sbase = smem_u32(smem);
    const int tid = threadIdx.x;
    const int wid = tid >> 5;      // warp = d-plane (0..7)
    const int lane = tid & 31;
    const int r4 = lane >> 2;      // w voxel (A row) / co (B col)
    const int c4 = lane & 3;       // k-group (0..3)
    const int b = blockIdx.y;
    const int blk = blockIdx.x;

    // level + tile decode
    int l = 0;
#pragma unroll
    for (int i = 1; i < NLEV; i++)
        if (blk >= c_tblk[i]) l = i;
    const int lblk = blk - c_tblk[l];
    const int R = c_res[l];
    const int off = c_off[l];
    const int nt = c_nt[l];
    const int tz = lblk / (nt * nt);
    const int trem = lblk - tz * nt * nt;
    const int ty = trem / nt;
    const int tx = trem - ty * nt;

    // ---- stage weights (pi mapping: k-group c4 <-> ci 4c4..4c4+3) ----
    // b0nh = (W[4c4][8nh+r4], W[4c4+1][8nh+r4]), b1nh = (W[4c4+2][..], W[4c4+3][..])
    {
        const float* wl = wgt + l * 6912;
        const int ci0 = 4 * c4;
        for (int tap = wid; tap < 27; tap += 8) {
            const float* wp = wl + tap * 256;
            const unsigned b00 = packh2(wp[ci0 * 16 + r4],       wp[(ci0 + 1) * 16 + r4]);
            const unsigned b10 = packh2(wp[(ci0 + 2) * 16 + r4], wp[(ci0 + 3) * 16 + r4]);
            const unsigned b01 = packh2(wp[ci0 * 16 + r4 + 8],       wp[(ci0 + 1) * 16 + r4 + 8]);
            const unsigned b11 = packh2(wp[(ci0 + 2) * 16 + r4 + 8], wp[(ci0 + 3) * 16 + r4 + 8]);
            asm volatile("st.shared.v4.b32 [%0], {%1,%2,%3,%4};"
                         :: "r"(sbase + SM_W + (unsigned)(tap * 512 + lane * 16)),
                            "r"(b00), "r"(b10), "r"(b01), "r"(b11) : "memory");
        }
        if (tid < 16)
            *(float*)(smem + SM_BIAS + tid * 4) = bias[l * 16 + tid];
    }

    // ---- stage input tile 10x10x10 (fp16, halo zero) ----
    // lane -> (voxel v = g0 + r4, chunk q = c4): one 16B LDG, ONE STS.64 at
    // granule v*32 + 8*c4. Incremental (dz,hy,wx) coords (v += 64 per round).
    {
        const int d0 = tz * 8 - 1, h0 = ty * 8 - 1, w0 = tx * 8 - 1;
        const float* inB = in + ((size_t)b * TOTAL_N + off) * 16;
        int v = wid * 8 + r4;
        int dz = 0, hy = v / 10, wx = v - hy * 10;   // v < 64 < 100 initially
        unsigned sa = sbase + SM_A + (unsigned)(v * 32 + c4 * 8);
#pragma unroll 4
        for (int rd = 0; rd < 16; rd++) {
            if (v < 1000) {
                const int dd = d0 + dz, hh = h0 + hy, ww = w0 + wx;
                unsigned p0 = 0u, p1 = 0u;
                if (((unsigned)dd < (unsigned)R) & ((unsigned)hh < (unsigned)R) &
                    ((unsigned)ww < (unsigned)R)) {
                    const float4 f = __ldg((const float4*)(inB +
                                     (size_t)((dd * R + hh) * R + ww) * 16) + c4);
                    p0 = packh2(f.x, f.y);
                    p1 = packh2(f.z, f.w);
                }
                asm volatile("st.shared.v2.b32 [%0], {%1,%2};"
                             :: "r"(sa), "r"(p0), "r"(p1) : "memory");
            }
            // v += 64: wx += 4, hy += 6, with single carries
            v += 64; sa += 64 * 32;
            wx += 4; hy += 6;
            if (wx >= 10) { wx -= 10; hy += 1; }
            if (hy >= 10) { hy -= 10; dz += 1; }
        }
    }
    __syncthreads();

    // ---- accumulators [h-pair j][nh][4], bias-initialized ----
    float acc[4][2][4];
    {
        const float* bs = (const float*)(smem + SM_BIAS);
        float b00 = bs[2 * c4], b01 = bs[2 * c4 + 1];
        float b10 = bs[2 * c4 + 8], b11 = bs[2 * c4 + 9];
#pragma unroll
        for (int j = 0; j < 4; j++) {
            acc[j][0][0] = b00; acc[j][0][1] = b01; acc[j][0][2] = b00; acc[j][0][3] = b01;
            acc[j][1][0] = b10; acc[j][1][1] = b11; acc[j][1][2] = b10; acc[j][1][3] = b11;
        }
    }

    const unsigned aBase = sbase + SM_A + (unsigned)(r4 * 32 + c4 * 8);
    const unsigned wBase = sbase + SM_W + (unsigned)(lane * 16);

// STEP at h-pair (lo,hi): j, weights W; A-frag = (lo.x, hi.x, lo.y, hi.y)
#define STEP(j, W, lo, hi)                                                      \
    mma_f16(acc[j][0], (lo).x, (hi).x, (lo).y, (hi).y, (W).x, (W).y);           \
    mma_f16(acc[j][1], (lo).x, (hi).x, (lo).y, (hi).y, (W).z, (W).w);

    for (int kd = 0; kd < 3; kd++) {
        const unsigned pb = aBase + (unsigned)((wid + kd) * 3200);
        const unsigned wkd = wBase + (unsigned)(kd * 9) * 512;
#pragma unroll
        for (int kw = 0; kw < 3; kw++) {
            const unsigned rb = pb + (unsigned)(kw * 32);
            const uint4 w0 = lds128(wkd + (unsigned)(kw * 512));          // kh=0
            const uint4 w1 = lds128(wkd + (unsigned)((3 + kw) * 512));    // kh=1
            const uint4 w2 = lds128(wkd + (unsigned)((6 + kw) * 512));    // kh=2
            // depth-4 rotation, 2-row lookahead (rows h0..h9 at stride 320B)
            uint2 r0 = lds64(rb);                 // h0
            uint2 r1 = lds64(rb + 320);           // h1
            uint2 r2 = lds64(rb + 640);           // h2
            STEP(0, w0, r0, r1);                  // pair(0,1)
            uint2 r3 = lds64(rb + 960);           // h3
            STEP(0, w1, r1, r2);                  // pair(1,2)
            r0 = lds64(rb + 1280);                // h4
            STEP(1, w0, r2, r3);                  // pair(2,3)
            STEP(0, w2, r2, r3);
            r1 = lds64(rb + 1600);                // h5
            STEP(1, w1, r3, r0);                  // pair(3,4)
            r2 = lds64(rb + 1920);                // h6
            STEP(2, w0, r0, r1);                  // pair(4,5)
            STEP(1, w2, r0, r1);
            r3 = lds64(rb + 2240);                // h7
            STEP(2, w1, r1, r2);                  // pair(5,6)
            r0 = lds64(rb + 2560);                // h8
            STEP(3, w0, r2, r3);                  // pair(6,7)
            STEP(2, w2, r2, r3);
            r1 = lds64(rb + 2880);                // h9
            STEP(3, w1, r3, r0);                  // pair(7,8)
            STEP(3, w2, r0, r1);                  // pair(8,9)
        }
    }
#undef STEP

    // ---- epilogue ----
    const int ow = tx * 8 + r4;
    const int od = tz * 8 + wid;
    float* outB = out + ((size_t)b * TOTAL_N + off) * 16;
    if (ow < R && od < R) {
#pragma unroll
        for (int j = 0; j < 4; j++) {
#pragma unroll
            for (int hl = 0; hl < 2; hl++) {
                const int oh = ty * 8 + j * 2 + hl;
                if (oh >= R) continue;
                float* po = outB + (size_t)((od * R + oh) * R + ow) * 16;
                *(float2*)(po + 2 * c4)     = make_float2(acc[j][0][hl * 2], acc[j][0][hl * 2 + 1]);
                *(float2*)(po + 2 * c4 + 8) = make_float2(acc[j][1][hl * 2], acc[j][1][hl * 2 + 1]);
            }
        }
    }
}

extern "C" void kernel_launch(void* const* d_in, const int* in_sizes, int n_in,
                              void* d_out, int out_size) {
    const float* in   = (const float*)d_in[0];
    const float* wgt  = (const float*)d_in[1];
    const float* bias = (const float*)d_in[2];
    float* out = (float*)d_out;

    static int configured = 0;
    if (!configured) {
        cudaFuncSetAttribute(conv3d_f16r_kernel,
                             cudaFuncAttributeMaxDynamicSharedMemorySize,
                             SM_TOTAL);
        configured = 1;
    }

    dim3 grid(4022, 2);
    conv3d_f16r_kernel<<<grid, TPB, SM_TOTAL>>>(in, wgt, bias, out);
}

// round 17
// speedup vs baseline: 1.4309x; 1.0641x over previous
#include <cuda_runtime.h>
#include <cuda_fp16.h>

// AbstractConv3D: 16 levels, dense R^3 grids, 3x3x3 conv, Cin=Cout=16, B=2.
// R17 = R14 fragment roles + R16 scheduling/occupancy:
//   A = weights (M=16 co x K=16 ci): one LDS.128/tap -> native consecutive quad.
//   B = voxels  (K=16 ci x N=8 w):   one LDS.64/h-row -> native (b0,b1) pair.
//   ZERO register marshaling MOVs. pi k-mapping (k-group q <-> ci 4q..4q+3) so
//   staging stays one STS.64/lane. Depth-4 B-row rotation with 2-3 row
//   lookahead. 8^3 tile, one d-plane/warp, 4 CTAs/SM.

#define NLEV 16
#define TPB 256
#define TOTAL_N 1844282

__constant__ int c_res[NLEV]  = {16,18,20,22,24,27,30,34,38,42,47,52,58,64,72,80};
__constant__ int c_off[NLEV]  = {0,4096,9928,17928,28576,42400,62083,89083,128387,
                                 183259,257347,361170,501778,696890,959034,1332282};
__constant__ int c_nt[NLEV]   = {2,3,3,3,3,4,4,5,5,6,6,7,8,8,9,10};   // ceil(R/8)
__constant__ int c_tblk[NLEV+1] = {0,8,35,62,89,116,180,244,369,494,710,926,
                                   1269,1781,2293,3022,4022};

// smem (bytes):
// [0,13824)     weights A-frag native: [tap][lane][a0..a3] (pi k-map)
// [13824,13888) bias f32
// [13888,45888) input tile fp16: 1000 granules x 32B, g = dz*100 + hy*10 + wx
//   granule byte [8q..8q+8) = ci(4q,4q+1 | 4q+2,4q+3)
#define SM_W    0
#define SM_BIAS 13824
#define SM_A    13888
#define SM_TOTAL 45888

__device__ __forceinline__ unsigned smem_u32(const void* p) {
    unsigned a;
    asm("{ .reg .u64 t; cvta.to.shared.u64 t, %1; cvt.u32.u64 %0, t; }"
        : "=r"(a) : "l"(p));
    return a;
}
__device__ __forceinline__ unsigned packh2(float lo, float hi) {
    __half2 h = __floats2half2_rn(lo, hi);
    return *(unsigned*)&h;
}
__device__ __forceinline__ uint2 lds64(unsigned a) {
    uint2 v;
    asm volatile("ld.shared.v2.b32 {%0,%1}, [%2];" : "=r"(v.x), "=r"(v.y) : "r"(a));
    return v;
}
__device__ __forceinline__ uint4 lds128(unsigned a) {
    uint4 v;
    asm volatile("ld.shared.v4.b32 {%0,%1,%2,%3}, [%4];"
                 : "=r"(v.x), "=r"(v.y), "=r"(v.z), "=r"(v.w) : "r"(a));
    return v;
}
// C += A(native quad) * B(native pair)
__device__ __forceinline__ void mma_f16(float* c, const uint4& a, const uint2& b) {
    asm volatile(
        "mma.sync.aligned.m16n8k16.row.col.f32.f16.f16.f32 "
        "{%0,%1,%2,%3}, {%4,%5,%6,%7}, {%8,%9}, {%0,%1,%2,%3};"
        : "+f"(c[0]), "+f"(c[1]), "+f"(c[2]), "+f"(c[3])
        : "r"(a.x), "r"(a.y), "r"(a.z), "r"(a.w), "r"(b.x), "r"(b.y));
}

__global__ __launch_bounds__(TPB, 4)
void conv3d_f16n_kernel(const float* __restrict__ in,
                        const float* __restrict__ wgt,
                        const float* __restrict__ bias,
                        float* __restrict__ out) {
    extern __shared__ char smem[];
    const unsigned sbase = smem_u32(smem);
    const int tid = threadIdx.x;
    const int wid = tid >> 5;      // warp = d-plane (0..7)
    const int lane = tid & 31;
    const int r4 = lane >> 2;      // co row (A/C m); B col voxel n
    const int c4 = lane & 3;       // k-group (0..3)
    const int b = blockIdx.y;
    const int blk = blockIdx.x;

    // level + tile decode
    int l = 0;
#pragma unroll
    for (int i = 1; i < NLEV; i++)
        if (blk >= c_tblk[i]) l = i;
    const int lblk = blk - c_tblk[l];
    const int R = c_res[l];
    const int off = c_off[l];
    const int nt = c_nt[l];
    const int tz = lblk / (nt * nt);
    const int trem = lblk - tz * nt * nt;
    const int ty = trem / nt;
    const int tx = trem - ty * nt;

    // ---- stage weights as native A-frag quads (pi k-map: k-grp q = ci 4q..4q+3)
    // a0 = (co r4,  ci 4c4,4c4+1)  a1 = (co r4+8, ci 4c4,4c4+1)
    // a2 = (co r4,  ci 4c4+2,+3)   a3 = (co r4+8, ci 4c4+2,+3)
    {
        const float* wl = wgt + l * 6912;
        const int ci0 = 4 * c4;
        for (int tap = wid; tap < 27; tap += 8) {
            const float* wp = wl + tap * 256;
            const unsigned a0 = packh2(wp[ci0 * 16 + r4],       wp[(ci0 + 1) * 16 + r4]);
            const unsigned a1 = packh2(wp[ci0 * 16 + r4 + 8],   wp[(ci0 + 1) * 16 + r4 + 8]);
            const unsigned a2 = packh2(wp[(ci0 + 2) * 16 + r4],     wp[(ci0 + 3) * 16 + r4]);
            const unsigned a3 = packh2(wp[(ci0 + 2) * 16 + r4 + 8], wp[(ci0 + 3) * 16 + r4 + 8]);
            asm volatile("st.shared.v4.b32 [%0], {%1,%2,%3,%4};"
                         :: "r"(sbase + SM_W + (unsigned)(tap * 512 + lane * 16)),
                            "r"(a0), "r"(a1), "r"(a2), "r"(a3) : "memory");
        }
        if (tid < 16)
            *(float*)(smem + SM_BIAS + tid * 4) = bias[l * 16 + tid];
    }

    // ---- stage input tile 10x10x10 (fp16, halo zero, one STS.64/lane) ----
    {
        const int d0 = tz * 8 - 1, h0 = ty * 8 - 1, w0 = tx * 8 - 1;
        const float* inB = in + ((size_t)b * TOTAL_N + off) * 16;
        int v = wid * 8 + r4;
        int dz = 0, hy = v / 10, wx = v - hy * 10;
        unsigned sa = sbase + SM_A + (unsigned)(v * 32 + c4 * 8);
#pragma unroll 4
        for (int rd = 0; rd < 16; rd++) {
            if (v < 1000) {
                const int dd = d0 + dz, hh = h0 + hy, ww = w0 + wx;
                unsigned p0 = 0u, p1 = 0u;
                if (((unsigned)dd < (unsigned)R) & ((unsigned)hh < (unsigned)R) &
                    ((unsigned)ww < (unsigned)R)) {
                    const float4 f = __ldg((const float4*)(inB +
                                     (size_t)((dd * R + hh) * R + ww) * 16) + c4);
                    p0 = packh2(f.x, f.y);
                    p1 = packh2(f.z, f.w);
                }
                asm volatile("st.shared.v2.b32 [%0], {%1,%2};"
                             :: "r"(sa), "r"(p0), "r"(p1) : "memory");
            }
            v += 64; sa += 64 * 32;
            wx += 4; hy += 6;
            if (wx >= 10) { wx -= 10; hy += 1; }
            if (hy >= 10) { hy -= 10; dz += 1; }
        }
    }
    __syncthreads();

    // ---- accumulators [h-row o][4]: c0/c1 = co r4 @ w 2c4,2c4+1 ;
    //                                 c2/c3 = co r4+8 ----
    float acc[8][4];
    {
        const float* bs = (const float*)(smem + SM_BIAS);
        const float bl = bs[r4], bh = bs[r4 + 8];
#pragma unroll
        for (int o = 0; o < 8; o++) {
            acc[o][0] = bl; acc[o][1] = bl;
            acc[o][2] = bh; acc[o][3] = bh;
        }
    }

    const unsigned wBase = sbase + SM_W + (unsigned)(lane * 16);
    const unsigned aBase = sbase + SM_A + (unsigned)(r4 * 32 + c4 * 8);

    for (int kd = 0; kd < 3; kd++) {
        const unsigned pb = aBase + (unsigned)((wid + kd) * 3200);
        const unsigned wkd = wBase + (unsigned)(kd * 9) * 512;
#pragma unroll
        for (int kw = 0; kw < 3; kw++) {
            const unsigned rb = pb + (unsigned)(kw * 32);
            const uint4 A0 = lds128(wkd + (unsigned)(kw * 512));          // kh=0
            const uint4 A1 = lds128(wkd + (unsigned)((3 + kw) * 512));    // kh=1
            const uint4 A2 = lds128(wkd + (unsigned)((6 + kw) * 512));    // kh=2
            // stream B rows h0..h9 (stride 320B), depth-4 rotation, 2-3 row lookahead
            uint2 t0 = lds64(rb);                  // h0
            uint2 t1 = lds64(rb + 320);            // h1
            uint2 t2 = lds64(rb + 640);            // h2
            mma_f16(acc[0], A0, t0);                               // row0
            uint2 t3 = lds64(rb + 960);            // h3
            mma_f16(acc[1], A0, t1); mma_f16(acc[0], A1, t1);      // row1
            t0 = lds64(rb + 1280);                 // h4
            mma_f16(acc[2], A0, t2); mma_f16(acc[1], A1, t2);
            mma_f16(acc[0], A2, t2);                               // row2
            t1 = lds64(rb + 1600);                 // h5
            mma_f16(acc[3], A0, t3); mma_f16(acc[2], A1, t3);
            mma_f16(acc[1], A2, t3);                               // row3
            t2 = lds64(rb + 1920);                 // h6
            mma_f16(acc[4], A0, t0); mma_f16(acc[3], A1, t0);
            mma_f16(acc[2], A2, t0);                               // row4
            t3 = lds64(rb + 2240);                 // h7
            mma_f16(acc[5], A0, t1); mma_f16(acc[4], A1, t1);
            mma_f16(acc[3], A2, t1);                               // row5
            t0 = lds64(rb + 2560);                 // h8
            mma_f16(acc[6], A0, t2); mma_f16(acc[5], A1, t2);
            mma_f16(acc[4], A2, t2);                               // row6
            t1 = lds64(rb + 2880);                 // h9
            mma_f16(acc[7], A0, t3); mma_f16(acc[6], A1, t3);
            mma_f16(acc[5], A2, t3);                               // row7
            mma_f16(acc[7], A1, t0); mma_f16(acc[6], A2, t0);      // row8
            mma_f16(acc[7], A2, t1);                               // row9
        }
    }

    // ---- epilogue: thread writes (co r4, r4+8) at voxels w = 2c4, 2c4+1 ----
    const int od = tz * 8 + wid;
    const int ow0 = tx * 8 + 2 * c4;
    float* outB = out + ((size_t)b * TOTAL_N + off) * 16;
    if (od < R) {
        const bool k0 = ow0 < R;
        const bool k1 = ow0 + 1 < R;
#pragma unroll
        for (int o = 0; o < 8; o++) {
            const int oh = ty * 8 + o;
            if (oh >= R) continue;
            float* pb2 = outB + (size_t)((od * R + oh) * R) * 16;
            if (k0) {
                pb2[(size_t)ow0 * 16 + r4]     = acc[o][0];
                pb2[(size_t)ow0 * 16 + r4 + 8] = acc[o][2];
            }
            if (k1) {
                pb2[(size_t)(ow0 + 1) * 16 + r4]     = acc[o][1];
                pb2[(size_t)(ow0 + 1) * 16 + r4 + 8] = acc[o][3];
            }
        }
    }
}

extern "C" void kernel_launch(void* const* d_in, const int* in_sizes, int n_in,
                              void* d_out, int out_size) {
    const float* in   = (const float*)d_in[0];
    const float* wgt  = (const float*)d_in[1];
    const float* bias = (const float*)d_in[2];
    float* out = (float*)d_out;

    static int configured = 0;
    if (!configured) {
        cudaFuncSetAttribute(conv3d_f16n_kernel,
                             cudaFuncAttributeMaxDynamicSharedMemorySize,
                             SM_TOTAL);
        configured = 1;
    }

    dim3 grid(4022, 2);
    conv3d_f16n_kernel<<<grid, TPB, SM_TOTAL>>>(in, wgt, bias, out);
}